// round 16
// baseline (speedup 1.0000x reference)
#include <cuda_runtime.h>
#include <cuda_fp16.h>
#include <cstdint>
#include <math.h>

#define TT 2048
#define DM 768
#define NH 12
#define DH 64
#define DHID 3072
#define SH 36            // smem row stride in uint32 words (32 data pairs + 4 pad)

// ---------------- scratch (device globals; no allocation) ----------------
__device__ __half g_h[TT * DM];
__device__ __half g_q[TT * DM];
__device__ __half g_k[TT * DM];
__device__ __half g_q2[TT * DM];
__device__ __half g_k2[TT * DM];
__device__ __half g_vT[DM * TT];     // per-head transposed V: vT[dim][token]
__device__ __half g_z[TT * DM];
__device__ float  g_x1[TT * DM];
__device__ __half g_h2[TT * DM];
__device__ __half g_hidden[TT * DHID];

// fp16 weights
__device__ __half hWq[DM * DM];
__device__ __half hWk[DM * DM];
__device__ __half hWq2[DM * DM];
__device__ __half hWk2[DM * DM];
__device__ __half hWv[DM * DM];
__device__ __half hWo[DM * DM];
__device__ __half hWp1[DHID * DM];
__device__ __half hWp2[DHID * DM];
__device__ __half hWd[DM * DHID];

// ---------------- helpers ----------------
__device__ __forceinline__ void cpa(uint32_t dst, const void* src) {
    asm volatile("cp.async.ca.shared.global [%0], [%1], 16;" :: "r"(dst), "l"(src));
}
__device__ __forceinline__ void cpcommit() { asm volatile("cp.async.commit_group;"); }
template <int N> __device__ __forceinline__ void cpwait() {
    asm volatile("cp.async.wait_group %0;" :: "n"(N));
}
__device__ __forceinline__ void mma16(float* d, const uint32_t* a, const uint32_t* b) {
    asm volatile(
        "mma.sync.aligned.m16n8k16.row.col.f32.f16.f16.f32 "
        "{%0,%1,%2,%3},{%4,%5,%6,%7},{%8,%9},{%0,%1,%2,%3};\n"
        : "+f"(d[0]), "+f"(d[1]), "+f"(d[2]), "+f"(d[3])
        : "r"(a[0]), "r"(a[1]), "r"(a[2]), "r"(a[3]), "r"(b[0]), "r"(b[1]));
}
__device__ __forceinline__ void ldsm4(uint32_t* r, uint32_t addr) {
    asm volatile("ldmatrix.sync.aligned.m8n8.x4.shared.b16 {%0,%1,%2,%3}, [%4];"
        : "=r"(r[0]), "=r"(r[1]), "=r"(r[2]), "=r"(r[3]) : "r"(addr));
}
__device__ __forceinline__ uint32_t packh(float a, float b) {
    __half2 h = __floats2half2_rn(a, b);
    return *(uint32_t*)&h;
}

#define A_LDSM_OFF(wmv, lanev) (((wmv) + ((lanev) & 15)) * SH + (((lanev) & 16) ? 4 : 0))
#define B_LDSM_OFF(c0v, lanev) (((c0v) + ((lanev) & 7) + (((lanev) & 16) ? 8 : 0)) * SH + (((lanev) & 8) ? 4 : 0))

// ---------------- RMSNorm (warp per row) + fused QKV-weight convert ----------------
struct W5 { const float* s[5]; };
#define QKV_F4 737280     // 5 * 147456 float4
__global__ __launch_bounds__(256) void rms_cvt(const float* __restrict__ x,
                                               __half* __restrict__ o, W5 w) {
    if (blockIdx.x < TT / 8) {
        int row = blockIdx.x * 8 + (threadIdx.x >> 5);
        int lane = threadIdx.x & 31;
        const float4* xr = (const float4*)(x + (size_t)row * DM);
        float4 v[6];
        float s = 0.f;
        #pragma unroll
        for (int i = 0; i < 6; i++) {
            v[i] = xr[lane + 32 * i];
            s += v[i].x * v[i].x + v[i].y * v[i].y + v[i].z * v[i].z + v[i].w * v[i].w;
        }
        #pragma unroll
        for (int off = 16; off; off >>= 1) s += __shfl_xor_sync(0xffffffffu, s, off);
        float scale = rsqrtf(s / (float)DM + 1e-6f);
        uint2* orow = (uint2*)(o + (size_t)row * DM);
        #pragma unroll
        for (int i = 0; i < 6; i++) {
            uint2 u;
            u.x = packh(v[i].x * scale, v[i].y * scale);
            u.y = packh(v[i].z * scale, v[i].w * scale);
            orow[lane + 32 * i] = u;
        }
    } else {
        int idx0 = (blockIdx.x - TT / 8) * 256 + threadIdx.x;
        int stride = (gridDim.x - TT / 8) * 256;
        for (int i = idx0; i < QKV_F4; i += stride) {
            int wi = i / 147456, off = i % 147456;
            float4 v = ((const float4*)w.s[wi])[off];
            __half2* d = (__half2*)((wi == 0) ? hWq : (wi == 1) ? hWk :
                                    (wi == 2) ? hWq2 : (wi == 3) ? hWk2 : hWv);
            d[2 * off]     = __floats2half2_rn(v.x, v.y);
            d[2 * off + 1] = __floats2half2_rn(v.z, v.w);
        }
    }
}

// ---------------- plain RMSNorm (second call) ----------------
__global__ __launch_bounds__(256) void rmsnorm_w(const float* __restrict__ x,
                                                 __half* __restrict__ o) {
    int row = blockIdx.x * 8 + (threadIdx.x >> 5);
    int lane = threadIdx.x & 31;
    const float4* xr = (const float4*)(x + (size_t)row * DM);
    float4 v[6];
    float s = 0.f;
    #pragma unroll
    for (int i = 0; i < 6; i++) {
        v[i] = xr[lane + 32 * i];
        s += v[i].x * v[i].x + v[i].y * v[i].y + v[i].z * v[i].z + v[i].w * v[i].w;
    }
    #pragma unroll
    for (int off = 16; off; off >>= 1) s += __shfl_xor_sync(0xffffffffu, s, off);
    float scale = rsqrtf(s / (float)DM + 1e-6f);
    uint2* orow = (uint2*)(o + (size_t)row * DM);
    #pragma unroll
    for (int i = 0; i < 6; i++) {
        uint2 u;
        u.x = packh(v[i].x * scale, v[i].y * scale);
        u.y = packh(v[i].z * scale, v[i].w * scale);
        orow[lane + 32 * i] = u;
    }
}

// ================= geometry (2-stage pipelines — proven R11 config) =================
#define AW (128 * SH)
#define BW (64 * SH)
#define BW2 (128 * SH)
#define GEMM2_SMEM ((2 * AW + 2 * BW2) * 4)    // proj: BM=128, BN=128 (73728 B)
#define DUAL_SMEM ((2 * AW + 4 * BW) * 4)
#define GEMM64_SMEM (4 * BW * 4)

// ---------------- fused 5-projection GEMM (BM=128,BN=128) + RoPE epilogue ----------------
__global__ __launch_bounds__(256, 2) void gemm_proj() {
    extern __shared__ uint32_t sm[];
    uint32_t sb = (uint32_t)__cvta_generic_to_shared(sm);
    int widx = blockIdx.x / 6;
    int bn = (blockIdx.x % 6) * 128;
    int bm = blockIdx.y * 128;
    const __half* Bw = (widx == 0) ? hWq : (widx == 1) ? hWk : (widx == 2) ? hWq2
                       : (widx == 3) ? hWk2 : hWv;
    int tid = threadIdx.x, wid = tid >> 5, lane = tid & 31;
    int g = lane >> 2, t = lane & 3;
    int wm = (wid & 3) * 32, wn = (wid >> 2) * 64;
    int a_off = A_LDSM_OFF(wm, lane);
    int b_off = B_LDSM_OFF(wn, lane);
    const __half* Ab = g_h + (size_t)bm * DM;
    const __half* Bb = Bw + (size_t)bn * DM;
    float acc[2][8][4] = {};
    {
        #pragma unroll
        for (int i = tid; i < 1024; i += 256) { int r = i >> 3, c = i & 7;
            cpa(sb + (r * SH + c * 4) * 4, Ab + (size_t)r * DM + c * 8);
            cpa(sb + (2 * AW + r * SH + c * 4) * 4, Bb + (size_t)r * DM + c * 8); }
        cpcommit();
    }
    const int nk = DM / 64;
    for (int it = 0; it < nk; it++) {
        int cur = it & 1;
        if (it + 1 < nk) {
            int k0 = (it + 1) * 64, nxt = cur ^ 1;
            #pragma unroll
            for (int i = tid; i < 1024; i += 256) { int r = i >> 3, c = i & 7;
                cpa(sb + (nxt * AW + r * SH + c * 4) * 4, Ab + (size_t)r * DM + k0 + c * 8);
                cpa(sb + (2 * AW + nxt * BW2 + r * SH + c * 4) * 4, Bb + (size_t)r * DM + k0 + c * 8); }
            cpcommit();
            cpwait<1>();
        } else cpwait<0>();
        __syncthreads();
        uint32_t regA = cur * AW;
        uint32_t regB = 2 * AW + cur * BW2;
        #pragma unroll
        for (int kk = 0; kk < 4; kk++) {
            int kb = kk * 8;
            uint32_t af0[4], af1[4], b01[4], b23[4], b45[4], b67[4];
            ldsm4(af0, sb + (regA + a_off + kb) * 4);
            ldsm4(af1, sb + (regA + a_off + 16 * SH + kb) * 4);
            ldsm4(b01, sb + (regB + b_off + kb) * 4);
            ldsm4(b23, sb + (regB + b_off + 16 * SH + kb) * 4);
            ldsm4(b45, sb + (regB + b_off + 32 * SH + kb) * 4);
            ldsm4(b67, sb + (regB + b_off + 48 * SH + kb) * 4);
            mma16(acc[0][0], af0, b01); mma16(acc[0][1], af0, b01 + 2);
            mma16(acc[0][2], af0, b23); mma16(acc[0][3], af0, b23 + 2);
            mma16(acc[0][4], af0, b45); mma16(acc[0][5], af0, b45 + 2);
            mma16(acc[0][6], af0, b67); mma16(acc[0][7], af0, b67 + 2);
            mma16(acc[1][0], af1, b01); mma16(acc[1][1], af1, b01 + 2);
            mma16(acc[1][2], af1, b23); mma16(acc[1][3], af1, b23 + 2);
            mma16(acc[1][4], af1, b45); mma16(acc[1][5], af1, b45 + 2);
            mma16(acc[1][6], af1, b67); mma16(acc[1][7], af1, b67 + 2);
        }
        __syncthreads();
    }
    if (widx < 4) {
        // ---- RoPE fused epilogue (tile spans 2 heads of 64 cols each) ----
        __half* C = (widx == 0) ? g_q : (widx == 1) ? g_k : (widx == 2) ? g_q2 : g_k2;
        float* Sg = (float*)sm;  // 128 x 128, stride 132 floats (67584 B <= 73728)
        #pragma unroll
        for (int mt = 0; mt < 2; mt++)
            #pragma unroll
            for (int nt = 0; nt < 8; nt++) {
                int c = wn + nt * 8 + 2 * t;
                #pragma unroll
                for (int half = 0; half < 2; half++) {
                    int r = wm + mt * 16 + g + half * 8;
                    *(float2*)(Sg + r * 132 + c) =
                        make_float2(acc[mt][nt][half * 2], acc[mt][nt][half * 2 + 1]);
                }
            }
        __syncthreads();
        #pragma unroll
        for (int i = tid; i < 2048; i += 256) {
            int r = i >> 4, j = i & 15;
            int head = j >> 3;
            int f = (j & 7) * 4;
            int u0 = head * 64 + f;
            int token = bm + r;
            float4 a4 = *(float4*)(Sg + r * 132 + u0);
            float4 b4 = *(float4*)(Sg + r * 132 + u0 + 32);
            float oa[4], ob[4];
            #pragma unroll
            for (int d = 0; d < 4; d++) {
                float inv = exp2f(-(float)(f + d) * 0.4152410118609203f);
                float ang = (float)token * inv;
                float sn, cs;
                sincosf(ang, &sn, &cs);
                float av = (&a4.x)[d], bv = (&b4.x)[d];
                oa[d] = av * cs + bv * sn;
                ob[d] = -av * sn + bv * cs;
            }
            uint2 va, vb;
            va.x = packh(oa[0], oa[1]); va.y = packh(oa[2], oa[3]);
            vb.x = packh(ob[0], ob[1]); vb.y = packh(ob[2], ob[3]);
            *(uint2*)(C + (size_t)token * DM + bn + u0) = va;
            *(uint2*)(C + (size_t)token * DM + bn + u0 + 32) = vb;
        }
    } else {
        // V: write transposed vT[col][row] (scattered stores — DRAM has headroom)
        #pragma unroll
        for (int mt = 0; mt < 2; mt++)
            #pragma unroll
            for (int nt = 0; nt < 8; nt++) {
                int c = bn + wn + nt * 8 + 2 * t;
                #pragma unroll
                for (int half = 0; half < 2; half++) {
                    int r = bm + wm + mt * 16 + g + half * 8;
                    g_vT[(size_t)c * TT + r]       = __float2half_rn(acc[mt][nt][half * 2]);
                    g_vT[(size_t)(c + 1) * TT + r] = __float2half_rn(acc[mt][nt][half * 2 + 1]);
                }
            }
    }
}

// ---------------- BM=64 fp16 GEMM NT, fp32 out (+res +bias), N=DM ----------------
__global__ __launch_bounds__(256, 3) void gemm_hf64(
    const __half* __restrict__ A, const __half* __restrict__ B, float* __restrict__ C,
    int K, const float* __restrict__ res, const float* __restrict__ bias) {
    extern __shared__ uint32_t sm[];
    uint32_t sb = (uint32_t)__cvta_generic_to_shared(sm);
    int bm = blockIdx.y * 64, bn = blockIdx.x * 64;
    int tid = threadIdx.x, wid = tid >> 5, lane = tid & 31;
    int g = lane >> 2, t = lane & 3;
    int wm = (wid & 3) * 16, wn = (wid >> 2) * 32;
    int a_off = A_LDSM_OFF(wm, lane);
    int b_off = B_LDSM_OFF(wn, lane);
    const __half* Ab = A + (size_t)bm * K;
    const __half* Bb = B + (size_t)bn * K;
    float acc[4][4] = {};
    {
        #pragma unroll
        for (int i = tid; i < 512; i += 256) { int r = i >> 3, c = i & 7;
            cpa(sb + (r * SH + c * 4) * 4, Ab + (size_t)r * K + c * 8);
            cpa(sb + (2 * BW + r * SH + c * 4) * 4, Bb + (size_t)r * K + c * 8); }
        cpcommit();
    }
    int nk = K >> 6;
    for (int it = 0; it < nk; it++) {
        int cur = it & 1;
        if (it + 1 < nk) {
            int k0 = (it + 1) << 6, nxt = cur ^ 1;
            #pragma unroll
            for (int i = tid; i < 512; i += 256) { int r = i >> 3, c = i & 7;
                cpa(sb + (nxt * BW + r * SH + c * 4) * 4, Ab + (size_t)r * K + k0 + c * 8);
                cpa(sb + (2 * BW + nxt * BW + r * SH + c * 4) * 4, Bb + (size_t)r * K + k0 + c * 8); }
            cpcommit();
            cpwait<1>();
        } else cpwait<0>();
        __syncthreads();
        uint32_t regA = cur * BW;
        uint32_t regB = 2 * BW + cur * BW;
        #pragma unroll
        for (int kk = 0; kk < 4; kk++) {
            int kb = kk * 8;
            uint32_t af[4], b01[4], b23[4];
            ldsm4(af, sb + (regA + a_off + kb) * 4);
            ldsm4(b01, sb + (regB + b_off + kb) * 4);
            ldsm4(b23, sb + (regB + b_off + 16 * SH + kb) * 4);
            mma16(acc[0], af, b01); mma16(acc[1], af, b01 + 2);
            mma16(acc[2], af, b23); mma16(acc[3], af, b23 + 2);
        }
        __syncthreads();
    }
    #pragma unroll
    for (int nt = 0; nt < 4; nt++) {
        int c = bn + wn + nt * 8 + 2 * t;
        #pragma unroll
        for (int half = 0; half < 2; half++) {
            int r = bm + wm + g + half * 8;
            float2 v = make_float2(acc[nt][half * 2], acc[nt][half * 2 + 1]);
            if (res) { float2 rr = *(const float2*)(res + (size_t)r * DM + c); v.x += rr.x; v.y += rr.y; }
            if (bias) { v.x += bias[c]; v.y += bias[c + 1]; }
            *(float2*)(C + (size_t)r * DM + c) = v;
        }
    }
}

// ---------------- dual gated GEMM: hidden = (h2@Wp1^T)*(h2@Wp2^T), fp16 out ----------------
__global__ __launch_bounds__(256, 2) void gemm_dual() {
    extern __shared__ uint32_t sm[];
    uint32_t sb = (uint32_t)__cvta_generic_to_shared(sm);
    int bm = blockIdx.y * 128, bn = blockIdx.x * 64;
    int tid = threadIdx.x, wid = tid >> 5, lane = tid & 31;
    int g = lane >> 2, t = lane & 3;
    int wm = (wid & 3) * 32, wn = (wid >> 2) * 32;
    int a_off = A_LDSM_OFF(wm, lane);
    int b_off = B_LDSM_OFF(wn, lane);
    const __half* Ab = g_h2 + (size_t)bm * DM;
    const __half* B1b = hWp1 + (size_t)bn * DM;
    const __half* B2b = hWp2 + (size_t)bn * DM;
    float acc1[2][4][4] = {};
    float acc2[2][4][4] = {};
    {
        #pragma unroll
        for (int i = tid; i < 1024; i += 256) { int r = i >> 3, c = i & 7;
            cpa(sb + (r * SH + c * 4) * 4, Ab + (size_t)r * DM + c * 8); }
        #pragma unroll
        for (int i = tid; i < 512; i += 256) { int r = i >> 3, c = i & 7;
            cpa(sb + (2 * AW + r * SH + c * 4) * 4, B1b + (size_t)r * DM + c * 8);
            cpa(sb + (2 * AW + 2 * BW + r * SH + c * 4) * 4, B2b + (size_t)r * DM + c * 8); }
        cpcommit();
    }
    const int nk = DM / 64;
    for (int it = 0; it < nk; it++) {
        int cur = it & 1;
        if (it + 1 < nk) {
            int k0 = (it + 1) * 64, nxt = cur ^ 1;
            #pragma unroll
            for (int i = tid; i < 1024; i += 256) { int r = i >> 3, c = i & 7;
                cpa(sb + (nxt * AW + r * SH + c * 4) * 4, Ab + (size_t)r * DM + k0 + c * 8); }
            #pragma unroll
            for (int i = tid; i < 512; i += 256) { int r = i >> 3, c = i & 7;
                cpa(sb + (2 * AW + nxt * BW + r * SH + c * 4) * 4, B1b + (size_t)r * DM + k0 + c * 8);
                cpa(sb + (2 * AW + 2 * BW + nxt * BW + r * SH + c * 4) * 4, B2b + (size_t)r * DM + k0 + c * 8); }
            cpcommit();
            cpwait<1>();
        } else cpwait<0>();
        __syncthreads();
        uint32_t regA = cur * AW;
        uint32_t regB1 = 2 * AW + cur * BW;
        uint32_t regB2 = 2 * AW + 2 * BW + cur * BW;
        #pragma unroll
        for (int kk = 0; kk < 4; kk++) {
            int kb = kk * 8;
            uint32_t af0[4], af1[4], c01[4], c23[4], d01[4], d23[4];
            ldsm4(af0, sb + (regA + a_off + kb) * 4);
            ldsm4(af1, sb + (regA + a_off + 16 * SH + kb) * 4);
            ldsm4(c01, sb + (regB1 + b_off + kb) * 4);
            ldsm4(c23, sb + (regB1 + b_off + 16 * SH + kb) * 4);
            ldsm4(d01, sb + (regB2 + b_off + kb) * 4);
            ldsm4(d23, sb + (regB2 + b_off + 16 * SH + kb) * 4);
            mma16(acc1[0][0], af0, c01); mma16(acc1[0][1], af0, c01 + 2);
            mma16(acc1[0][2], af0, c23); mma16(acc1[0][3], af0, c23 + 2);
            mma16(acc1[1][0], af1, c01); mma16(acc1[1][1], af1, c01 + 2);
            mma16(acc1[1][2], af1, c23); mma16(acc1[1][3], af1, c23 + 2);
            mma16(acc2[0][0], af0, d01); mma16(acc2[0][1], af0, d01 + 2);
            mma16(acc2[0][2], af0, d23); mma16(acc2[0][3], af0, d23 + 2);
            mma16(acc2[1][0], af1, d01); mma16(acc2[1][1], af1, d01 + 2);
            mma16(acc2[1][2], af1, d23); mma16(acc2[1][3], af1, d23 + 2);
        }
        __syncthreads();
    }
    #pragma unroll
    for (int mt = 0; mt < 2; mt++)
        #pragma unroll
        for (int nt = 0; nt < 4; nt++) {
            int c = bn + wn + nt * 8 + 2 * t;
            #pragma unroll
            for (int half = 0; half < 2; half++) {
                int r = bm + wm + mt * 16 + g + half * 8;
                *(uint32_t*)(g_hidden + (size_t)r * DHID + c) =
                    packh(acc1[mt][nt][half * 2] * acc2[mt][nt][half * 2],
                          acc1[mt][nt][half * 2 + 1] * acc2[mt][nt][half * 2 + 1]);
            }
        }
}

// ---------------- attention + fused late-weight conversion plane ----------------
struct W4 { const float* s[4]; };   // Wo, Wp1, Wp2, Wd (fp32 sources)
#define REST_F4 1916928             // 147456 + 3*589824 float4
#define ATW 2304
#define ATT_SMEM (8 * ATW * 4)
__global__ __launch_bounds__(256, 2) void attn_h(W4 w4) {
    extern __shared__ uint32_t sm[];
    int hd = blockIdx.y;
    int tid = threadIdx.x;
    if (hd == NH) {
        // converter plane: stream Wo/Wp1/Wp2/Wd fp32 -> fp16 alongside attention
        int idx0 = blockIdx.x * 256 + tid;
        int stride = gridDim.x * 256;
        for (int i = idx0; i < REST_F4; i += stride) {
            int wi, off;
            if (i < 147456) { wi = 0; off = i; }
            else { int j = i - 147456; wi = 1 + j / 589824; off = j % 589824; }
            float4 v = ((const float4*)w4.s[wi])[off];
            __half2* d = (__half2*)((wi == 0) ? hWo : (wi == 1) ? hWp1 :
                                    (wi == 2) ? hWp2 : hWd);
            d[2 * off]     = __floats2half2_rn(v.x, v.y);
            d[2 * off + 1] = __floats2half2_rn(v.z, v.w);
        }
        return;
    }
    uint32_t sb = (uint32_t)__cvta_generic_to_shared(sm);
    int qt = (int)gridDim.x - 1 - (int)blockIdx.x;
    int wid = tid >> 5, lane = tid & 31;
    int g = lane >> 2, t = lane & 3;
    int wm = (wid & 3) * 16;
    int wh = wid >> 2;
    int wn = wh * 32;
    int wnp = wh * 16;
    int hoff = hd * DH;
    int a_off = A_LDSM_OFF(wm, lane);
    int bk_off = B_LDSM_OFF(wn, lane);
    int v_off = B_LDSM_OFF(0, lane);

    #pragma unroll
    for (int i = tid; i < 512; i += 256) {
        int r = i >> 3, c = i & 7;
        size_t go = (size_t)(qt * 64 + r) * DM + hoff + c * 8;
        cpa(sb + (7 * ATW + r * SH + c * 4) * 4, g_q + go);
        cpa(sb + (r * SH + c * 4) * 4, g_q2 + go);
    }
    cpcommit();
    #pragma unroll
    for (int i = tid; i < 512; i += 256) {
        int r = i >> 3, c = i & 7;
        size_t go = (size_t)r * DM + hoff + c * 8;
        cpa(sb + (1 * ATW + r * SH + c * 4) * 4, g_k + go);
        cpa(sb + (3 * ATW + r * SH + c * 4) * 4, g_k2 + go);
        cpa(sb + (5 * ATW + r * SH + c * 4) * 4, g_vT + (size_t)(hoff + r) * TT + c * 8);
    }
    cpcommit();
    cpwait<1>();
    __syncthreads();

    uint32_t aq[4][4];
    #pragma unroll
    for (int kk = 0; kk < 4; kk++)
        ldsm4(aq[kk], sb + (7 * ATW + a_off + kk * 8) * 4);

    float zacc[8][4] = {};
    for (int st = 0; st <= qt; st++) {
        int buf = st & 1;
        if (st < qt) {
            int sn = st + 1, nb = buf ^ 1;
            #pragma unroll
            for (int i = tid; i < 512; i += 256) {
                int r = i >> 3, c = i & 7;
                size_t go = (size_t)(sn * 64 + r) * DM + hoff + c * 8;
                cpa(sb + ((1 + nb) * ATW + r * SH + c * 4) * 4, g_k + go);
                cpa(sb + ((3 + nb) * ATW + r * SH + c * 4) * 4, g_k2 + go);
                cpa(sb + ((5 + nb) * ATW + r * SH + c * 4) * 4,
                    g_vT + (size_t)(hoff + r) * TT + sn * 64 + c * 8);
            }
            cpcommit();
            cpwait<1>();
        } else cpwait<0>();
        __syncthreads();
        uint32_t regK  = (1 + buf) * ATW;
        uint32_t regK2 = (3 + buf) * ATW;
        uint32_t regV  = (5 + buf) * ATW;

        float s1[4][4] = {}, s2[4][4] = {};
        #pragma unroll
        for (int kk = 0; kk < 4; kk++) {
            int kb = kk * 8;
            uint32_t aq2[4], k01[4], k23[4], l01[4], l23[4];
            ldsm4(aq2, sb + (0 + a_off + kb) * 4);
            ldsm4(k01, sb + (regK + bk_off + kb) * 4);
            ldsm4(k23, sb + (regK + bk_off + 16 * SH + kb) * 4);
            ldsm4(l01, sb + (regK2 + bk_off + kb) * 4);
            ldsm4(l23, sb + (regK2 + bk_off + 16 * SH + kb) * 4);
            mma16(s1[0], aq[kk], k01); mma16(s1[1], aq[kk], k01 + 2);
            mma16(s1[2], aq[kk], k23); mma16(s1[3], aq[kk], k23 + 2);
            mma16(s2[0], aq2, l01); mma16(s2[1], aq2, l01 + 2);
            mma16(s2[2], aq2, l23); mma16(s2[3], aq2, l23 + 2);
        }

        uint32_t pa[2][4];
        #pragma unroll
        for (int kc = 0; kc < 2; kc++) {
            #pragma unroll
            for (int sub = 0; sub < 2; sub++) {
                int nt = 2 * kc + sub;
                float p0 = s1[nt][0] * s2[nt][0] * (1.f / 4096.f);
                float p1 = s1[nt][1] * s2[nt][1] * (1.f / 4096.f);
                float p2 = s1[nt][2] * s2[nt][2] * (1.f / 4096.f);
                float p3 = s1[nt][3] * s2[nt][3] * (1.f / 4096.f);
                if (st == qt) {
                    int rlo = wm + g, rhi = rlo + 8;
                    int sc = wn + nt * 8 + 2 * t;
                    if (sc > rlo) p0 = 0.f;
                    if (sc + 1 > rlo) p1 = 0.f;
                    if (sc > rhi) p2 = 0.f;
                    if (sc + 1 > rhi) p3 = 0.f;
                }
                pa[kc][sub * 2]     = packh(p0, p1);
                pa[kc][sub * 2 + 1] = packh(p2, p3);
            }
        }

        #pragma unroll
        for (int kc = 0; kc < 2; kc++) {
            int kw = wnp + kc * 8;
            uint32_t v01[4], v23[4], v45[4], v67[4];
            ldsm4(v01, sb + (regV + v_off + kw) * 4);
            ldsm4(v23, sb + (regV + v_off + 16 * SH + kw) * 4);
            ldsm4(v45, sb + (regV + v_off + 32 * SH + kw) * 4);
            ldsm4(v67, sb + (regV + v_off + 48 * SH + kw) * 4);
            mma16(zacc[0], pa[kc], v01); mma16(zacc[1], pa[kc], v01 + 2);
            mma16(zacc[2], pa[kc], v23); mma16(zacc[3], pa[kc], v23 + 2);
            mma16(zacc[4], pa[kc], v45); mma16(zacc[5], pa[kc], v45 + 2);
            mma16(zacc[6], pa[kc], v67); mma16(zacc[7], pa[kc], v67 + 2);
        }
        __syncthreads();
    }

    float* Sg = (float*)(sm + 1 * ATW);
    if (wh == 1) {
        #pragma unroll
        for (int nt = 0; nt < 8; nt++) {
            int c = nt * 8 + 2 * t;
            #pragma unroll
            for (int half = 0; half < 2; half++) {
                int r = wm + g + half * 8;
                *(float2*)(Sg + r * 68 + c) =
                    make_float2(zacc[nt][half * 2], zacc[nt][half * 2 + 1]);
            }
        }
    }
    __syncthreads();
    if (wh == 0) {
        #pragma unroll
        for (int nt = 0; nt < 8; nt++) {
            int c = nt * 8 + 2 * t;
            #pragma unroll
            for (int half = 0; half < 2; half++) {
                int rl = wm + g + half * 8;
                float2 o = *(float2*)(Sg + rl * 68 + c);
                int r = qt * 64 + rl;
                *(uint32_t*)(g_z + (size_t)r * DM + hoff + c) =
                    packh(zacc[nt][half * 2] + o.x, zacc[nt][half * 2 + 1] + o.y);
            }
        }
    }
}

// ---------------- launch ----------------
extern "C" void kernel_launch(void* const* d_in, const int* in_sizes, int n_in,
                              void* d_out, int out_size) {
    const float* x = (const float*)d_in[0];
    const float* bd = (const float*)d_in[10];

    __half *z_p, *hWo_p, *hidden_p, *hWd_p, *h_p, *h2_p;
    float* x1_p;
    cudaGetSymbolAddress((void**)&z_p, g_z);
    cudaGetSymbolAddress((void**)&hWo_p, hWo);
    cudaGetSymbolAddress((void**)&hidden_p, g_hidden);
    cudaGetSymbolAddress((void**)&hWd_p, hWd);
    cudaGetSymbolAddress((void**)&x1_p, g_x1);
    cudaGetSymbolAddress((void**)&h_p, g_h);
    cudaGetSymbolAddress((void**)&h2_p, g_h2);

    cudaFuncSetAttribute(gemm_proj, cudaFuncAttributeMaxDynamicSharedMemorySize, GEMM2_SMEM);
    cudaFuncSetAttribute(gemm_hf64, cudaFuncAttributeMaxDynamicSharedMemorySize, GEMM64_SMEM);
    cudaFuncSetAttribute(gemm_dual, cudaFuncAttributeMaxDynamicSharedMemorySize, DUAL_SMEM);
    cudaFuncSetAttribute(attn_h, cudaFuncAttributeMaxDynamicSharedMemorySize, ATT_SMEM);

    // 1. rmsnorm + QKV weight conversion (fused, independent work)
    W5 w5;
    for (int i = 0; i < 5; i++) w5.s[i] = (const float*)d_in[1 + i];
    rms_cvt<<<TT / 8 + 64, 256>>>(x, h_p, w5);

    // 2. projections + RoPE fused
    gemm_proj<<<dim3(30, TT / 128), 256, GEMM2_SMEM>>>();

    // 3. attention + late-weight conversion plane (hd == NH)
    W4 w4;
    w4.s[0] = (const float*)d_in[6];   // Wo
    w4.s[1] = (const float*)d_in[7];   // Wp1
    w4.s[2] = (const float*)d_in[8];   // Wp2
    w4.s[3] = (const float*)d_in[9];   // Wd
    attn_h<<<dim3(TT / 64, NH + 1), 256, ATT_SMEM>>>(w4);

    // 4. Wo + residual
    gemm_hf64<<<dim3(DM / 64, TT / 64), 256, GEMM64_SMEM>>>(z_p, hWo_p, x1_p, DM, x, nullptr);

    // 5. rmsnorm 2
    rmsnorm_w<<<TT / 8, 256>>>(x1_p, h2_p);

    // 6. gated MLP up
    gemm_dual<<<dim3(DHID / 64, TT / 128), 256, DUAL_SMEM>>>();

    // 7. down proj + residual + bias
    gemm_hf64<<<dim3(DM / 64, TT / 64), 256, GEMM64_SMEM>>>(hidden_p, hWd_p, (float*)d_out, DHID, x1_p, bd);
}

// round 17
// speedup vs baseline: 1.8840x; 1.8840x over previous
#include <cuda_runtime.h>
#include <cuda_fp16.h>
#include <cstdint>
#include <math.h>

#define TT 2048
#define DM 768
#define NH 12
#define DH 64
#define DHID 3072
#define SH 36            // smem row stride in uint32 words (32 data pairs + 4 pad)

// ---------------- scratch (device globals; no allocation) ----------------
__device__ __half g_h[TT * DM];
__device__ __half g_q[TT * DM];
__device__ __half g_k[TT * DM];
__device__ __half g_q2[TT * DM];
__device__ __half g_k2[TT * DM];
__device__ __half g_vT[DM * TT];     // per-head transposed V: vT[dim][token]
__device__ __half g_z[TT * DM];
__device__ float  g_x1[TT * DM];
__device__ __half g_h2[TT * DM];
__device__ __half g_hidden[TT * DHID];

// fp16 weights
__device__ __half hWq[DM * DM];
__device__ __half hWk[DM * DM];
__device__ __half hWq2[DM * DM];
__device__ __half hWk2[DM * DM];
__device__ __half hWv[DM * DM];
__device__ __half hWo[DM * DM];
__device__ __half hWp1[DHID * DM];
__device__ __half hWp2[DHID * DM];
__device__ __half hWd[DM * DHID];

// ---------------- helpers ----------------
__device__ __forceinline__ void cpa(uint32_t dst, const void* src) {
    asm volatile("cp.async.ca.shared.global [%0], [%1], 16;" :: "r"(dst), "l"(src));
}
__device__ __forceinline__ void cpcommit() { asm volatile("cp.async.commit_group;"); }
template <int N> __device__ __forceinline__ void cpwait() {
    asm volatile("cp.async.wait_group %0;" :: "n"(N));
}
__device__ __forceinline__ void mma16(float* d, const uint32_t* a, const uint32_t* b) {
    asm volatile(
        "mma.sync.aligned.m16n8k16.row.col.f32.f16.f16.f32 "
        "{%0,%1,%2,%3},{%4,%5,%6,%7},{%8,%9},{%0,%1,%2,%3};\n"
        : "+f"(d[0]), "+f"(d[1]), "+f"(d[2]), "+f"(d[3])
        : "r"(a[0]), "r"(a[1]), "r"(a[2]), "r"(a[3]), "r"(b[0]), "r"(b[1]));
}
__device__ __forceinline__ void ldsm4(uint32_t* r, uint32_t addr) {
    asm volatile("ldmatrix.sync.aligned.m8n8.x4.shared.b16 {%0,%1,%2,%3}, [%4];"
        : "=r"(r[0]), "=r"(r[1]), "=r"(r[2]), "=r"(r[3]) : "r"(addr));
}
__device__ __forceinline__ uint32_t packh(float a, float b) {
    __half2 h = __floats2half2_rn(a, b);
    return *(uint32_t*)&h;
}

#define A_LDSM_OFF(wmv, lanev) (((wmv) + ((lanev) & 15)) * SH + (((lanev) & 16) ? 4 : 0))
#define B_LDSM_OFF(c0v, lanev) (((c0v) + ((lanev) & 7) + (((lanev) & 16) ? 8 : 0)) * SH + (((lanev) & 8) ? 4 : 0))

// ---------------- weight convert fp32 -> fp16 (rn) ----------------
struct W9 { const float* s[9]; };
__device__ __forceinline__ __half* wdst(int wi) {
    switch (wi) {
        case 0: return hWq;  case 1: return hWk;  case 2: return hWq2;
        case 3: return hWk2; case 4: return hWv;  case 5: return hWo;
        case 6: return hWp1; case 7: return hWp2; default: return hWd;
    }
}
#define NF4 2654208
__global__ void cvtw_all(W9 w) {
    int i = blockIdx.x * 256 + threadIdx.x;
    if (i >= NF4) return;
    int wi; int off;
    if (i < 884736) { wi = i / 147456; off = i % 147456; }
    else { int j = i - 884736; wi = 6 + j / 589824; off = j % 589824; }
    float4 v = ((const float4*)w.s[wi])[off];
    __half2* d = (__half2*)wdst(wi);
    d[2 * off]     = __floats2half2_rn(v.x, v.y);
    d[2 * off + 1] = __floats2half2_rn(v.z, v.w);
}

// ---------------- RMSNorm: warp per row, 8 rows/CTA ----------------
__global__ __launch_bounds__(256) void rmsnorm_w(const float* __restrict__ x,
                                                 __half* __restrict__ o) {
    int row = blockIdx.x * 8 + (threadIdx.x >> 5);
    int lane = threadIdx.x & 31;
    const float4* xr = (const float4*)(x + (size_t)row * DM);
    float4 v[6];
    float s = 0.f;
    #pragma unroll
    for (int i = 0; i < 6; i++) {
        v[i] = xr[lane + 32 * i];
        s += v[i].x * v[i].x + v[i].y * v[i].y + v[i].z * v[i].z + v[i].w * v[i].w;
    }
    #pragma unroll
    for (int off = 16; off; off >>= 1) s += __shfl_xor_sync(0xffffffffu, s, off);
    float scale = rsqrtf(s / (float)DM + 1e-6f);
    uint2* orow = (uint2*)(o + (size_t)row * DM);
    #pragma unroll
    for (int i = 0; i < 6; i++) {
        uint2 u;
        u.x = packh(v[i].x * scale, v[i].y * scale);
        u.y = packh(v[i].z * scale, v[i].w * scale);
        orow[lane + 32 * i] = u;
    }
}

// ================= geometry (2-stage pipelines — proven config) =================
#define AW (128 * SH)
#define BW (64 * SH)
#define BW2 (128 * SH)
#define GEMM2_SMEM ((2 * AW + 2 * BW2) * 4)    // proj: BM=128, BN=128 (73728 B)
#define DUAL_SMEM ((2 * AW + 4 * BW) * 4)
#define GEMM64_SMEM (4 * BW * 4)

// ---------------- fused 5-projection GEMM (BM=128,BN=128) + RoPE epilogue ----------------
__global__ __launch_bounds__(256, 2) void gemm_proj() {
    extern __shared__ uint32_t sm[];
    uint32_t sb = (uint32_t)__cvta_generic_to_shared(sm);
    int widx = blockIdx.x / 6;
    int bn = (blockIdx.x % 6) * 128;
    int bm = blockIdx.y * 128;
    const __half* Bw = (widx == 0) ? hWq : (widx == 1) ? hWk : (widx == 2) ? hWq2
                       : (widx == 3) ? hWk2 : hWv;
    int tid = threadIdx.x, wid = tid >> 5, lane = tid & 31;
    int g = lane >> 2, t = lane & 3;
    int wm = (wid & 3) * 32, wn = (wid >> 2) * 64;
    int a_off = A_LDSM_OFF(wm, lane);
    int b_off = B_LDSM_OFF(wn, lane);
    const __half* Ab = g_h + (size_t)bm * DM;
    const __half* Bb = Bw + (size_t)bn * DM;
    float acc[2][8][4] = {};
    {
        #pragma unroll
        for (int i = tid; i < 1024; i += 256) { int r = i >> 3, c = i & 7;
            cpa(sb + (r * SH + c * 4) * 4, Ab + (size_t)r * DM + c * 8);
            cpa(sb + (2 * AW + r * SH + c * 4) * 4, Bb + (size_t)r * DM + c * 8); }
        cpcommit();
    }
    const int nk = DM / 64;
    for (int it = 0; it < nk; it++) {
        int cur = it & 1;
        if (it + 1 < nk) {
            int k0 = (it + 1) * 64, nxt = cur ^ 1;
            #pragma unroll
            for (int i = tid; i < 1024; i += 256) { int r = i >> 3, c = i & 7;
                cpa(sb + (nxt * AW + r * SH + c * 4) * 4, Ab + (size_t)r * DM + k0 + c * 8);
                cpa(sb + (2 * AW + nxt * BW2 + r * SH + c * 4) * 4, Bb + (size_t)r * DM + k0 + c * 8); }
            cpcommit();
            cpwait<1>();
        } else cpwait<0>();
        __syncthreads();
        uint32_t regA = cur * AW;
        uint32_t regB = 2 * AW + cur * BW2;
        #pragma unroll
        for (int kk = 0; kk < 4; kk++) {
            int kb = kk * 8;
            uint32_t af0[4], af1[4], b01[4], b23[4], b45[4], b67[4];
            ldsm4(af0, sb + (regA + a_off + kb) * 4);
            ldsm4(af1, sb + (regA + a_off + 16 * SH + kb) * 4);
            ldsm4(b01, sb + (regB + b_off + kb) * 4);
            ldsm4(b23, sb + (regB + b_off + 16 * SH + kb) * 4);
            ldsm4(b45, sb + (regB + b_off + 32 * SH + kb) * 4);
            ldsm4(b67, sb + (regB + b_off + 48 * SH + kb) * 4);
            mma16(acc[0][0], af0, b01); mma16(acc[0][1], af0, b01 + 2);
            mma16(acc[0][2], af0, b23); mma16(acc[0][3], af0, b23 + 2);
            mma16(acc[0][4], af0, b45); mma16(acc[0][5], af0, b45 + 2);
            mma16(acc[0][6], af0, b67); mma16(acc[0][7], af0, b67 + 2);
            mma16(acc[1][0], af1, b01); mma16(acc[1][1], af1, b01 + 2);
            mma16(acc[1][2], af1, b23); mma16(acc[1][3], af1, b23 + 2);
            mma16(acc[1][4], af1, b45); mma16(acc[1][5], af1, b45 + 2);
            mma16(acc[1][6], af1, b67); mma16(acc[1][7], af1, b67 + 2);
        }
        __syncthreads();
    }
    if (widx < 4) {
        // ---- RoPE fused epilogue (tile spans 2 heads of 64 cols each) ----
        __half* C = (widx == 0) ? g_q : (widx == 1) ? g_k : (widx == 2) ? g_q2 : g_k2;
        float* Sg = (float*)sm;  // 128 x 128, stride 132 floats (67584 B <= 73728)
        #pragma unroll
        for (int mt = 0; mt < 2; mt++)
            #pragma unroll
            for (int nt = 0; nt < 8; nt++) {
                int c = wn + nt * 8 + 2 * t;
                #pragma unroll
                for (int half = 0; half < 2; half++) {
                    int r = wm + mt * 16 + g + half * 8;
                    *(float2*)(Sg + r * 132 + c) =
                        make_float2(acc[mt][nt][half * 2], acc[mt][nt][half * 2 + 1]);
                }
            }
        __syncthreads();
        #pragma unroll
        for (int i = tid; i < 2048; i += 256) {
            int r = i >> 4, j = i & 15;
            int head = j >> 3;
            int f = (j & 7) * 4;
            int u0 = head * 64 + f;
            int token = bm + r;
            float4 a4 = *(float4*)(Sg + r * 132 + u0);
            float4 b4 = *(float4*)(Sg + r * 132 + u0 + 32);
            float oa[4], ob[4];
            #pragma unroll
            for (int d = 0; d < 4; d++) {
                // 10000^(-(f+d)/32) = exp2(-(f+d)*log2(10000)/32)
                float inv = exp2f(-(float)(f + d) * 0.4152410118609203f);
                float ang = (float)token * inv;
                float sn, cs;
                sincosf(ang, &sn, &cs);
                float av = (&a4.x)[d], bv = (&b4.x)[d];
                oa[d] = av * cs + bv * sn;
                ob[d] = -av * sn + bv * cs;
            }
            uint2 va, vb;
            va.x = packh(oa[0], oa[1]); va.y = packh(oa[2], oa[3]);
            vb.x = packh(ob[0], ob[1]); vb.y = packh(ob[2], ob[3]);
            *(uint2*)(C + (size_t)token * DM + bn + u0) = va;
            *(uint2*)(C + (size_t)token * DM + bn + u0 + 32) = vb;
        }
    } else {
        // V: write transposed vT[col][row]
        #pragma unroll
        for (int mt = 0; mt < 2; mt++)
            #pragma unroll
            for (int nt = 0; nt < 8; nt++) {
                int c = bn + wn + nt * 8 + 2 * t;
                #pragma unroll
                for (int half = 0; half < 2; half++) {
                    int r = bm + wm + mt * 16 + g + half * 8;
                    g_vT[(size_t)c * TT + r]       = __float2half_rn(acc[mt][nt][half * 2]);
                    g_vT[(size_t)(c + 1) * TT + r] = __float2half_rn(acc[mt][nt][half * 2 + 1]);
                }
            }
    }
}

// ---------------- BM=64 fp16 GEMM NT, fp32 out (+res +bias), N=DM ----------------
__global__ __launch_bounds__(256, 3) void gemm_hf64(
    const __half* __restrict__ A, const __half* __restrict__ B, float* __restrict__ C,
    int K, const float* __restrict__ res, const float* __restrict__ bias) {
    extern __shared__ uint32_t sm[];
    uint32_t sb = (uint32_t)__cvta_generic_to_shared(sm);
    int bm = blockIdx.y * 64, bn = blockIdx.x * 64;
    int tid = threadIdx.x, wid = tid >> 5, lane = tid & 31;
    int g = lane >> 2, t = lane & 3;
    int wm = (wid & 3) * 16, wn = (wid >> 2) * 32;
    int a_off = A_LDSM_OFF(wm, lane);
    int b_off = B_LDSM_OFF(wn, lane);
    const __half* Ab = A + (size_t)bm * K;
    const __half* Bb = B + (size_t)bn * K;
    float acc[4][4] = {};
    {
        #pragma unroll
        for (int i = tid; i < 512; i += 256) { int r = i >> 3, c = i & 7;
            cpa(sb + (r * SH + c * 4) * 4, Ab + (size_t)r * K + c * 8);
            cpa(sb + (2 * BW + r * SH + c * 4) * 4, Bb + (size_t)r * K + c * 8); }
        cpcommit();
    }
    int nk = K >> 6;
    for (int it = 0; it < nk; it++) {
        int cur = it & 1;
        if (it + 1 < nk) {
            int k0 = (it + 1) << 6, nxt = cur ^ 1;
            #pragma unroll
            for (int i = tid; i < 512; i += 256) { int r = i >> 3, c = i & 7;
                cpa(sb + (nxt * BW + r * SH + c * 4) * 4, Ab + (size_t)r * K + k0 + c * 8);
                cpa(sb + (2 * BW + nxt * BW + r * SH + c * 4) * 4, Bb + (size_t)r * K + k0 + c * 8); }
            cpcommit();
            cpwait<1>();
        } else cpwait<0>();
        __syncthreads();
        uint32_t regA = cur * BW;
        uint32_t regB = 2 * BW + cur * BW;
        #pragma unroll
        for (int kk = 0; kk < 4; kk++) {
            int kb = kk * 8;
            uint32_t af[4], b01[4], b23[4];
            ldsm4(af, sb + (regA + a_off + kb) * 4);
            ldsm4(b01, sb + (regB + b_off + kb) * 4);
            ldsm4(b23, sb + (regB + b_off + 16 * SH + kb) * 4);
            mma16(acc[0], af, b01); mma16(acc[1], af, b01 + 2);
            mma16(acc[2], af, b23); mma16(acc[3], af, b23 + 2);
        }
        __syncthreads();
    }
    #pragma unroll
    for (int nt = 0; nt < 4; nt++) {
        int c = bn + wn + nt * 8 + 2 * t;
        #pragma unroll
        for (int half = 0; half < 2; half++) {
            int r = bm + wm + g + half * 8;
            float2 v = make_float2(acc[nt][half * 2], acc[nt][half * 2 + 1]);
            if (res) { float2 rr = *(const float2*)(res + (size_t)r * DM + c); v.x += rr.x; v.y += rr.y; }
            if (bias) { v.x += bias[c]; v.y += bias[c + 1]; }
            *(float2*)(C + (size_t)r * DM + c) = v;
        }
    }
}

// ---------------- dual gated GEMM: hidden = (h2@Wp1^T)*(h2@Wp2^T), fp16 out ----------------
__global__ __launch_bounds__(256, 2) void gemm_dual() {
    extern __shared__ uint32_t sm[];
    uint32_t sb = (uint32_t)__cvta_generic_to_shared(sm);
    int bm = blockIdx.y * 128, bn = blockIdx.x * 64;
    int tid = threadIdx.x, wid = tid >> 5, lane = tid & 31;
    int g = lane >> 2, t = lane & 3;
    int wm = (wid & 3) * 32, wn = (wid >> 2) * 32;
    int a_off = A_LDSM_OFF(wm, lane);
    int b_off = B_LDSM_OFF(wn, lane);
    const __half* Ab = g_h2 + (size_t)bm * DM;
    const __half* B1b = hWp1 + (size_t)bn * DM;
    const __half* B2b = hWp2 + (size_t)bn * DM;
    float acc1[2][4][4] = {};
    float acc2[2][4][4] = {};
    {
        #pragma unroll
        for (int i = tid; i < 1024; i += 256) { int r = i >> 3, c = i & 7;
            cpa(sb + (r * SH + c * 4) * 4, Ab + (size_t)r * DM + c * 8); }
        #pragma unroll
        for (int i = tid; i < 512; i += 256) { int r = i >> 3, c = i & 7;
            cpa(sb + (2 * AW + r * SH + c * 4) * 4, B1b + (size_t)r * DM + c * 8);
            cpa(sb + (2 * AW + 2 * BW + r * SH + c * 4) * 4, B2b + (size_t)r * DM + c * 8); }
        cpcommit();
    }
    const int nk = DM / 64;
    for (int it = 0; it < nk; it++) {
        int cur = it & 1;
        if (it + 1 < nk) {
            int k0 = (it + 1) * 64, nxt = cur ^ 1;
            #pragma unroll
            for (int i = tid; i < 1024; i += 256) { int r = i >> 3, c = i & 7;
                cpa(sb + (nxt * AW + r * SH + c * 4) * 4, Ab + (size_t)r * DM + k0 + c * 8); }
            #pragma unroll
            for (int i = tid; i < 512; i += 256) { int r = i >> 3, c = i & 7;
                cpa(sb + (2 * AW + nxt * BW + r * SH + c * 4) * 4, B1b + (size_t)r * DM + k0 + c * 8);
                cpa(sb + (2 * AW + 2 * BW + nxt * BW + r * SH + c * 4) * 4, B2b + (size_t)r * DM + k0 + c * 8); }
            cpcommit();
            cpwait<1>();
        } else cpwait<0>();
        __syncthreads();
        uint32_t regA = cur * AW;
        uint32_t regB1 = 2 * AW + cur * BW;
        uint32_t regB2 = 2 * AW + 2 * BW + cur * BW;
        #pragma unroll
        for (int kk = 0; kk < 4; kk++) {
            int kb = kk * 8;
            uint32_t af0[4], af1[4], c01[4], c23[4], d01[4], d23[4];
            ldsm4(af0, sb + (regA + a_off + kb) * 4);
            ldsm4(af1, sb + (regA + a_off + 16 * SH + kb) * 4);
            ldsm4(c01, sb + (regB1 + b_off + kb) * 4);
            ldsm4(c23, sb + (regB1 + b_off + 16 * SH + kb) * 4);
            ldsm4(d01, sb + (regB2 + b_off + kb) * 4);
            ldsm4(d23, sb + (regB2 + b_off + 16 * SH + kb) * 4);
            mma16(acc1[0][0], af0, c01); mma16(acc1[0][1], af0, c01 + 2);
            mma16(acc1[0][2], af0, c23); mma16(acc1[0][3], af0, c23 + 2);
            mma16(acc1[1][0], af1, c01); mma16(acc1[1][1], af1, c01 + 2);
            mma16(acc1[1][2], af1, c23); mma16(acc1[1][3], af1, c23 + 2);
            mma16(acc2[0][0], af0, d01); mma16(acc2[0][1], af0, d01 + 2);
            mma16(acc2[0][2], af0, d23); mma16(acc2[0][3], af0, d23 + 2);
            mma16(acc2[1][0], af1, d01); mma16(acc2[1][1], af1, d01 + 2);
            mma16(acc2[1][2], af1, d23); mma16(acc2[1][3], af1, d23 + 2);
        }
        __syncthreads();
    }
    #pragma unroll
    for (int mt = 0; mt < 2; mt++)
        #pragma unroll
        for (int nt = 0; nt < 4; nt++) {
            int c = bn + wn + nt * 8 + 2 * t;
            #pragma unroll
            for (int half = 0; half < 2; half++) {
                int r = bm + wm + mt * 16 + g + half * 8;
                *(uint32_t*)(g_hidden + (size_t)r * DHID + c) =
                    packh(acc1[mt][nt][half * 2] * acc2[mt][nt][half * 2],
                          acc1[mt][nt][half * 2 + 1] * acc2[mt][nt][half * 2 + 1]);
            }
        }
}

// ---------------- attention (ldmatrix fragments, P in regs, double-buffered) ----------------
#define ATW 2304
#define ATT_SMEM (8 * ATW * 4)
__global__ __launch_bounds__(256, 2) void attn_h() {
    extern __shared__ uint32_t sm[];
    uint32_t sb = (uint32_t)__cvta_generic_to_shared(sm);
    int hd = blockIdx.y;
    int qt = (int)gridDim.x - 1 - (int)blockIdx.x;
    int tid = threadIdx.x, wid = tid >> 5, lane = tid & 31;
    int g = lane >> 2, t = lane & 3;
    int wm = (wid & 3) * 16;
    int wh = wid >> 2;
    int wn = wh * 32;
    int wnp = wh * 16;
    int hoff = hd * DH;
    int a_off = A_LDSM_OFF(wm, lane);
    int bk_off = B_LDSM_OFF(wn, lane);
    int v_off = B_LDSM_OFF(0, lane);

    #pragma unroll
    for (int i = tid; i < 512; i += 256) {
        int r = i >> 3, c = i & 7;
        size_t go = (size_t)(qt * 64 + r) * DM + hoff + c * 8;
        cpa(sb + (7 * ATW + r * SH + c * 4) * 4, g_q + go);
        cpa(sb + (r * SH + c * 4) * 4, g_q2 + go);
    }
    cpcommit();
    #pragma unroll
    for (int i = tid; i < 512; i += 256) {
        int r = i >> 3, c = i & 7;
        size_t go = (size_t)r * DM + hoff + c * 8;
        cpa(sb + (1 * ATW + r * SH + c * 4) * 4, g_k + go);
        cpa(sb + (3 * ATW + r * SH + c * 4) * 4, g_k2 + go);
        cpa(sb + (5 * ATW + r * SH + c * 4) * 4, g_vT + (size_t)(hoff + r) * TT + c * 8);
    }
    cpcommit();
    cpwait<1>();
    __syncthreads();

    uint32_t aq[4][4];
    #pragma unroll
    for (int kk = 0; kk < 4; kk++)
        ldsm4(aq[kk], sb + (7 * ATW + a_off + kk * 8) * 4);

    float zacc[8][4] = {};
    for (int st = 0; st <= qt; st++) {
        int buf = st & 1;
        if (st < qt) {
            int sn = st + 1, nb = buf ^ 1;
            #pragma unroll
            for (int i = tid; i < 512; i += 256) {
                int r = i >> 3, c = i & 7;
                size_t go = (size_t)(sn * 64 + r) * DM + hoff + c * 8;
                cpa(sb + ((1 + nb) * ATW + r * SH + c * 4) * 4, g_k + go);
                cpa(sb + ((3 + nb) * ATW + r * SH + c * 4) * 4, g_k2 + go);
                cpa(sb + ((5 + nb) * ATW + r * SH + c * 4) * 4,
                    g_vT + (size_t)(hoff + r) * TT + sn * 64 + c * 8);
            }
            cpcommit();
            cpwait<1>();
        } else cpwait<0>();
        __syncthreads();
        uint32_t regK  = (1 + buf) * ATW;
        uint32_t regK2 = (3 + buf) * ATW;
        uint32_t regV  = (5 + buf) * ATW;

        float s1[4][4] = {}, s2[4][4] = {};
        #pragma unroll
        for (int kk = 0; kk < 4; kk++) {
            int kb = kk * 8;
            uint32_t aq2[4], k01[4], k23[4], l01[4], l23[4];
            ldsm4(aq2, sb + (0 + a_off + kb) * 4);
            ldsm4(k01, sb + (regK + bk_off + kb) * 4);
            ldsm4(k23, sb + (regK + bk_off + 16 * SH + kb) * 4);
            ldsm4(l01, sb + (regK2 + bk_off + kb) * 4);
            ldsm4(l23, sb + (regK2 + bk_off + 16 * SH + kb) * 4);
            mma16(s1[0], aq[kk], k01); mma16(s1[1], aq[kk], k01 + 2);
            mma16(s1[2], aq[kk], k23); mma16(s1[3], aq[kk], k23 + 2);
            mma16(s2[0], aq2, l01); mma16(s2[1], aq2, l01 + 2);
            mma16(s2[2], aq2, l23); mma16(s2[3], aq2, l23 + 2);
        }

        uint32_t pa[2][4];
        #pragma unroll
        for (int kc = 0; kc < 2; kc++) {
            #pragma unroll
            for (int sub = 0; sub < 2; sub++) {
                int nt = 2 * kc + sub;
                float p0 = s1[nt][0] * s2[nt][0] * (1.f / 4096.f);
                float p1 = s1[nt][1] * s2[nt][1] * (1.f / 4096.f);
                float p2 = s1[nt][2] * s2[nt][2] * (1.f / 4096.f);
                float p3 = s1[nt][3] * s2[nt][3] * (1.f / 4096.f);
                if (st == qt) {
                    int rlo = wm + g, rhi = rlo + 8;
                    int sc = wn + nt * 8 + 2 * t;
                    if (sc > rlo) p0 = 0.f;
                    if (sc + 1 > rlo) p1 = 0.f;
                    if (sc > rhi) p2 = 0.f;
                    if (sc + 1 > rhi) p3 = 0.f;
                }
                pa[kc][sub * 2]     = packh(p0, p1);
                pa[kc][sub * 2 + 1] = packh(p2, p3);
            }
        }

        #pragma unroll
        for (int kc = 0; kc < 2; kc++) {
            int kw = wnp + kc * 8;
            uint32_t v01[4], v23[4], v45[4], v67[4];
            ldsm4(v01, sb + (regV + v_off + kw) * 4);
            ldsm4(v23, sb + (regV + v_off + 16 * SH + kw) * 4);
            ldsm4(v45, sb + (regV + v_off + 32 * SH + kw) * 4);
            ldsm4(v67, sb + (regV + v_off + 48 * SH + kw) * 4);
            mma16(zacc[0], pa[kc], v01); mma16(zacc[1], pa[kc], v01 + 2);
            mma16(zacc[2], pa[kc], v23); mma16(zacc[3], pa[kc], v23 + 2);
            mma16(zacc[4], pa[kc], v45); mma16(zacc[5], pa[kc], v45 + 2);
            mma16(zacc[6], pa[kc], v67); mma16(zacc[7], pa[kc], v67 + 2);
        }
        __syncthreads();
    }

    float* Sg = (float*)(sm + 1 * ATW);
    if (wh == 1) {
        #pragma unroll
        for (int nt = 0; nt < 8; nt++) {
            int c = nt * 8 + 2 * t;
            #pragma unroll
            for (int half = 0; half < 2; half++) {
                int r = wm + g + half * 8;
                *(float2*)(Sg + r * 68 + c) =
                    make_float2(zacc[nt][half * 2], zacc[nt][half * 2 + 1]);
            }
        }
    }
    __syncthreads();
    if (wh == 0) {
        #pragma unroll
        for (int nt = 0; nt < 8; nt++) {
            int c = nt * 8 + 2 * t;
            #pragma unroll
            for (int half = 0; half < 2; half++) {
                int rl = wm + g + half * 8;
                float2 o = *(float2*)(Sg + rl * 68 + c);
                int r = qt * 64 + rl;
                *(uint32_t*)(g_z + (size_t)r * DM + hoff + c) =
                    packh(zacc[nt][half * 2] + o.x, zacc[nt][half * 2 + 1] + o.y);
            }
        }
    }
}

// ---------------- launch ----------------
extern "C" void kernel_launch(void* const* d_in, const int* in_sizes, int n_in,
                              void* d_out, int out_size) {
    const float* x = (const float*)d_in[0];
    const float* bd = (const float*)d_in[10];

    __half *z_p, *hWo_p, *hidden_p, *hWd_p, *h_p, *h2_p;
    float* x1_p;
    cudaGetSymbolAddress((void**)&z_p, g_z);
    cudaGetSymbolAddress((void**)&hWo_p, hWo);
    cudaGetSymbolAddress((void**)&hidden_p, g_hidden);
    cudaGetSymbolAddress((void**)&hWd_p, hWd);
    cudaGetSymbolAddress((void**)&x1_p, g_x1);
    cudaGetSymbolAddress((void**)&h_p, g_h);
    cudaGetSymbolAddress((void**)&h2_p, g_h2);

    cudaFuncSetAttribute(gemm_proj, cudaFuncAttributeMaxDynamicSharedMemorySize, GEMM2_SMEM);
    cudaFuncSetAttribute(gemm_hf64, cudaFuncAttributeMaxDynamicSharedMemorySize, GEMM64_SMEM);
    cudaFuncSetAttribute(gemm_dual, cudaFuncAttributeMaxDynamicSharedMemorySize, DUAL_SMEM);
    cudaFuncSetAttribute(attn_h, cudaFuncAttributeMaxDynamicSharedMemorySize, ATT_SMEM);

    W9 w;
    for (int i = 0; i < 9; i++) w.s[i] = (const float*)d_in[1 + i];
    cvtw_all<<<(NF4 + 255) / 256, 256>>>(w);

    rmsnorm_w<<<TT / 8, 256>>>(x, h_p);
    gemm_proj<<<dim3(30, TT / 128), 256, GEMM2_SMEM>>>();         // projections + RoPE fused
    attn_h<<<dim3(TT / 64, NH), 256, ATT_SMEM>>>();
    gemm_hf64<<<dim3(DM / 64, TT / 64), 256, GEMM64_SMEM>>>(z_p, hWo_p, x1_p, DM, x, nullptr);
    rmsnorm_w<<<TT / 8, 256>>>(x1_p, h2_p);
    gemm_dual<<<dim3(DHID / 64, TT / 128), 256, DUAL_SMEM>>>();
    gemm_hf64<<<dim3(DM / 64, TT / 64), 256, GEMM64_SMEM>>>(hidden_p, hWd_p, (float*)d_out, DHID, x1_p, bd);
}